// round 2
// baseline (speedup 1.0000x reference)
#include <cuda_runtime.h>

#define KB 16
#define SW 20
#define BN 512

__device__ __align__(16) float g_act0[32 * 21504];
__device__ __align__(16) float g_act1[32 * 16384];
__device__ __align__(16) float g_act2[32 * 4096];
__device__ __align__(16) float g_act3[32 * 4096];
__device__ __align__(16) float g_act4[32 * 64];
__device__ __align__(16) float g_part[16 * 32 * 4096]; // 2,097,152 floats (== 4*32*16384)

__device__ __forceinline__ void cp16(unsigned s, const float* g) {
    asm volatile("cp.async.cg.shared.global [%0], [%1], 16;" :: "r"(s), "l"(g));
}
__device__ __forceinline__ void lds_v2(unsigned long long &a, unsigned long long &b, unsigned addr) {
    asm("ld.shared.v2.b64 {%0, %1}, [%2];" : "=l"(a), "=l"(b) : "r"(addr));
}
__device__ __forceinline__ void fma2(unsigned long long &d, unsigned long long a, unsigned long long b) {
    asm("fma.rn.f32x2 %0, %1, %2, %0;" : "+l"(d) : "l"(a), "l"(b));
}

// ---------------- conv + permuted scatter ----------------
__global__ void conv_kernel(const float* __restrict__ in,
                            const float* __restrict__ cw,
                            const float* __restrict__ cb) {
    int b = blockIdx.x >> 2, f = blockIdx.x & 3, tid = threadIdx.x;
    __shared__ float xin[343], wsh[128], bsh[16];
    for (int i = tid; i < 343; i += 128) xin[i] = in[(b * 343 + i) * 5 + f];
    if (tid < 128) wsh[tid] = cw[tid];
    if (tid < 16)  bsh[tid] = cb[tid];
    __syncthreads();
    int h = b >> 4, base = (b & 15) * 1344 + f * 336;
    for (int l = tid; l < 336; l += 128) {
        #pragma unroll
        for (int c = 0; c < 16; ++c) {
            float s = bsh[c];
            #pragma unroll
            for (int k = 0; k < 8; ++k) s += xin[l + k] * wsh[c * 8 + k];
            g_act0[(2 * c + h) * 21504 + base + l] = fmaxf(s, 0.f);
        }
    }
}

// ---------------- fp32x2 GEMM, split-K partials ----------------
__device__ __forceinline__ const float* act_ptr(int s) {
    return s == 0 ? g_act0 : s == 1 ? g_act1 : s == 2 ? g_act2 : g_act3;
}

__global__ __launch_bounds__(256, 1)
void gemm_kernel(int xsel, const float* __restrict__ W, int N, int K, int nsteps) {
    extern __shared__ __align__(16) float smem[];
    float* ws = smem;                   // [2][BN*SW]
    float* xs = smem + 2 * BN * SW;     // [2][32*SW]
    const float* X = act_ptr(xsel);
    int tid = threadIdx.x, ntile = blockIdx.x * BN, ky = blockIdx.y;
    long k0 = (long)ky * nsteps * KB;
    int ng = tid & 63, b0 = (tid >> 6) * 8;
    unsigned ws_b = (unsigned)__cvta_generic_to_shared(ws);
    unsigned xs_b = (unsigned)__cvta_generic_to_shared(xs);

    unsigned long long acc[8][8];
    #pragma unroll
    for (int i = 0; i < 8; ++i)
        #pragma unroll
        for (int j = 0; j < 8; ++j) acc[i][j] = 0ull;

    const float* Wt = W + (long)ntile * K + k0;
    const float* Xt = X + k0;

    auto stage = [&](int buf, int c) {
        long kc = (long)c * KB;
        unsigned wd = ws_b + buf * (BN * SW * 4);
        #pragma unroll
        for (int it = 0; it < 8; ++it) {
            int o = it * 256 + tid, n = o >> 2, kq = o & 3;
            cp16(wd + (n * SW + kq * 4) * 4, Wt + (long)n * K + kc + kq * 4);
        }
        if (tid < 128) {
            int b = tid >> 2, kq = tid & 3;
            cp16(xs_b + buf * (32 * SW * 4) + (b * SW + kq * 4) * 4,
                 Xt + (long)b * K + kc + kq * 4);
        }
        asm volatile("cp.async.commit_group;");
    };

    stage(0, 0);
    for (int c = 0; c < nsteps; ++c) {
        int nb = c & 1;
        if (c + 1 < nsteps) stage(nb ^ 1, c + 1);
        else asm volatile("cp.async.commit_group;");
        asm volatile("cp.async.wait_group 1;");
        __syncthreads();
        unsigned wsa = ws_b + nb * (BN * SW * 4);
        unsigned xsa = xs_b + nb * (32 * SW * 4);
        #pragma unroll
        for (int kk = 0; kk < KB; kk += 4) {
            unsigned long long xa[8], xb[8];
            #pragma unroll
            for (int i = 0; i < 8; ++i)
                lds_v2(xa[i], xb[i], xsa + ((b0 + i) * SW + kk) * 4);
            #pragma unroll
            for (int j = 0; j < 8; ++j) {
                unsigned long long wa, wb;
                lds_v2(wa, wb, wsa + ((ng + 64 * j) * SW + kk) * 4);
                #pragma unroll
                for (int i = 0; i < 8; ++i) {
                    fma2(acc[i][j], xa[i], wa);
                    fma2(acc[i][j], xb[i], wb);
                }
            }
        }
        __syncthreads();
    }

    #pragma unroll
    for (int i = 0; i < 8; ++i)
        #pragma unroll
        for (int j = 0; j < 8; ++j) {
            unsigned long long v = acc[i][j];
            float s = __uint_as_float((unsigned)v) + __uint_as_float((unsigned)(v >> 32));
            g_part[((long)(ky * 32 + b0 + i)) * N + ntile + ng + 64 * j] = s;
        }
}

// ---------------- split-K reduce + bias + relu ----------------
__global__ void reduce_kernel(const float* __restrict__ bias, int osel, int N, int ks) {
    int idx = blockIdx.x * 256 + threadIdx.x;
    if (idx >= 32 * N) return;
    float s = bias[idx % N];
    for (int si = 0; si < ks; ++si) s += g_part[(long)si * 32 * N + idx];
    float* out = (osel == 1) ? g_act1 : (osel == 2) ? g_act2 : g_act3;
    out[idx] = fmaxf(s, 0.f);
}

// ---------------- dense4 (4096 -> 64) ----------------
__global__ void dense4_kernel(const float* __restrict__ w4, const float* __restrict__ b4) {
    int n = blockIdx.x, tid = threadIdx.x;
    float acc[32];
    #pragma unroll
    for (int b = 0; b < 32; ++b) acc[b] = 0.f;
    const float* wr = w4 + n * 4096;
    for (int k = tid; k < 4096; k += 128) {
        float w = wr[k];
        #pragma unroll
        for (int b = 0; b < 32; ++b) acc[b] += g_act3[b * 4096 + k] * w;
    }
    __shared__ float red[4][32];
    int lane = tid & 31, wrp = tid >> 5;
    #pragma unroll
    for (int b = 0; b < 32; ++b) {
        float v = acc[b];
        v += __shfl_down_sync(0xffffffffu, v, 16);
        v += __shfl_down_sync(0xffffffffu, v, 8);
        v += __shfl_down_sync(0xffffffffu, v, 4);
        v += __shfl_down_sync(0xffffffffu, v, 2);
        v += __shfl_down_sync(0xffffffffu, v, 1);
        if (lane == 0) red[wrp][b] = v;
    }
    __syncthreads();
    if (tid < 32) {
        float s = red[0][tid] + red[1][tid] + red[2][tid] + red[3][tid] + b4[n];
        g_act4[tid * 64 + n] = fmaxf(s, 0.f);
    }
}

// ---------------- fused output (64 -> 16 -> 1) ----------------
__global__ void final_kernel(const float* __restrict__ wo, const float* __restrict__ bo,
                             const float* __restrict__ wf, const float* __restrict__ bf,
                             float* __restrict__ out) {
    int b = threadIdx.x;   // 32 threads
    float res = bf[0];
    for (int j = 0; j < 16; ++j) {
        float o = bo[j];
        #pragma unroll
        for (int n = 0; n < 64; ++n) o += g_act4[b * 64 + n] * wo[j * 64 + n];
        res += o * wf[j];
    }
    out[b] = res;
}

extern "C" void kernel_launch(void* const* d_in, const int* in_sizes, int n_in,
                              void* d_out, int out_size) {
    const float* in  = (const float*)d_in[0];
    const float* cw  = (const float*)d_in[4];
    const float* cb  = (const float*)d_in[5];
    const float* w1  = (const float*)d_in[6];
    const float* b1  = (const float*)d_in[7];
    const float* w2  = (const float*)d_in[8];
    const float* b2  = (const float*)d_in[9];
    const float* w3  = (const float*)d_in[10];
    const float* b3  = (const float*)d_in[11];
    const float* w4  = (const float*)d_in[12];
    const float* b4  = (const float*)d_in[13];
    const float* wo  = (const float*)d_in[14];
    const float* bo  = (const float*)d_in[15];
    const float* wf  = (const float*)d_in[16];
    const float* bf  = (const float*)d_in[17];
    float* out = (float*)d_out;

    int smem = (2 * BN * SW + 2 * 32 * SW) * 4;  // 87040 B
    cudaFuncSetAttribute(gemm_kernel, cudaFuncAttributeMaxDynamicSharedMemorySize, smem);

    conv_kernel<<<128, 128>>>(in, cw, cb);

    gemm_kernel<<<dim3(32, 4), 256, smem>>>(0, w1, 16384, 21504, 336);
    reduce_kernel<<<2048, 256>>>(b1, 1, 16384, 4);

    gemm_kernel<<<dim3(8, 16), 256, smem>>>(1, w2, 4096, 16384, 64);
    reduce_kernel<<<512, 256>>>(b2, 2, 4096, 16);

    gemm_kernel<<<dim3(8, 16), 256, smem>>>(2, w3, 4096, 4096, 16);
    reduce_kernel<<<512, 256>>>(b3, 3, 4096, 16);

    dense4_kernel<<<64, 128>>>(w4, b4);
    final_kernel<<<1, 32>>>(wo, bo, wf, bf, out);
}

// round 3
// speedup vs baseline: 1.6516x; 1.6516x over previous
#include <cuda_runtime.h>

#define KB 16
#define SW 20
#define BN 512
#define STAGES 4

__device__ __align__(16) float g_act0[32 * 21504];
__device__ __align__(16) float g_act1[32 * 16384];
__device__ __align__(16) float g_act2[32 * 4096];
__device__ __align__(16) float g_act3[32 * 4096];
__device__ __align__(16) float g_act4[32 * 64];
__device__ __align__(16) float g_part[16 * 32 * 4096]; // == 4*32*16384

__device__ __forceinline__ void cp16(unsigned s, const float* g) {
    asm volatile("cp.async.cg.shared.global [%0], [%1], 16;" :: "r"(s), "l"(g));
}
__device__ __forceinline__ void lds_v2(unsigned long long &a, unsigned long long &b, unsigned addr) {
    asm("ld.shared.v2.b64 {%0, %1}, [%2];" : "=l"(a), "=l"(b) : "r"(addr));
}
__device__ __forceinline__ void fma2(unsigned long long &d, unsigned long long a, unsigned long long b) {
    asm("fma.rn.f32x2 %0, %1, %2, %0;" : "+l"(d) : "l"(a), "l"(b));
}

// ---------------- conv + permuted scatter ----------------
__global__ void conv_kernel(const float* __restrict__ in,
                            const float* __restrict__ cw,
                            const float* __restrict__ cb) {
    int b = blockIdx.x >> 2, f = blockIdx.x & 3, tid = threadIdx.x;
    __shared__ float xin[343], wsh[128], bsh[16];
    for (int i = tid; i < 343; i += 128) xin[i] = in[(b * 343 + i) * 5 + f];
    if (tid < 128) wsh[tid] = cw[tid];
    if (tid < 16)  bsh[tid] = cb[tid];
    __syncthreads();
    int h = b >> 4, base = (b & 15) * 1344 + f * 336;
    for (int l = tid; l < 336; l += 128) {
        #pragma unroll
        for (int c = 0; c < 16; ++c) {
            float s = bsh[c];
            #pragma unroll
            for (int k = 0; k < 8; ++k) s += xin[l + k] * wsh[c * 8 + k];
            g_act0[(2 * c + h) * 21504 + base + l] = fmaxf(s, 0.f);
        }
    }
}

// ---------------- fp32x2 GEMM, 4-stage cp.async pipeline, split-K ----------------
__device__ __forceinline__ const float* act_ptr(int s) {
    return s == 0 ? g_act0 : s == 1 ? g_act1 : s == 2 ? g_act2 : g_act3;
}

__global__ __launch_bounds__(256, 1)
void gemm_kernel(int xsel, const float* __restrict__ W, int N, int K, int nsteps) {
    extern __shared__ __align__(16) float smem[];
    // layout: STAGES buffers, each [BN*SW (W)] + [32*SW (X)]
    const int STB = (BN + 32) * SW;            // floats per stage
    float* base = smem;
    const float* X = act_ptr(xsel);
    int tid = threadIdx.x, ntile = blockIdx.x * BN, ky = blockIdx.y;
    long k0 = (long)ky * nsteps * KB;
    int ng = tid & 63, b0 = (tid >> 6) * 8;
    unsigned sm_b = (unsigned)__cvta_generic_to_shared(base);

    unsigned long long acc[8][8];
    #pragma unroll
    for (int i = 0; i < 8; ++i)
        #pragma unroll
        for (int j = 0; j < 8; ++j) acc[i][j] = 0ull;

    const float* Wt = W + (long)ntile * K + k0;
    const float* Xt = X + k0;

    auto stage = [&](int c) {
        int buf = ((unsigned)c) % STAGES;
        long kc = (long)c * KB;
        unsigned wd = sm_b + buf * (STB * 4);
        unsigned xd = wd + BN * SW * 4;
        #pragma unroll
        for (int it = 0; it < 8; ++it) {
            int o = it * 256 + tid, n = o >> 2, kq = o & 3;
            cp16(wd + (n * SW + kq * 4) * 4, Wt + (long)n * K + kc + kq * 4);
        }
        if (tid < 128) {
            int b = tid >> 2, kq = tid & 3;
            cp16(xd + (b * SW + kq * 4) * 4, Xt + (long)b * K + kc + kq * 4);
        }
    };

    // prologue: 3 stages in flight
    for (int c = 0; c < 3; ++c) {
        if (c < nsteps) stage(c);
        asm volatile("cp.async.commit_group;");
    }

    for (int c = 0; c < nsteps; ++c) {
        asm volatile("cp.async.wait_group 2;");
        __syncthreads();                 // stage c landed; buffer (c-1)%4 fully consumed
        if (c + 3 < nsteps) stage(c + 3);
        asm volatile("cp.async.commit_group;");

        int buf = ((unsigned)c) % STAGES;
        unsigned wsa = sm_b + buf * (STB * 4);
        unsigned xsa = wsa + BN * SW * 4;
        #pragma unroll
        for (int kk = 0; kk < KB; kk += 4) {
            unsigned long long xa[8], xb[8];
            #pragma unroll
            for (int i = 0; i < 8; ++i)
                lds_v2(xa[i], xb[i], xsa + ((b0 + i) * SW + kk) * 4);
            #pragma unroll
            for (int j = 0; j < 8; ++j) {
                unsigned long long wa, wb;
                lds_v2(wa, wb, wsa + ((ng + 64 * j) * SW + kk) * 4);
                #pragma unroll
                for (int i = 0; i < 8; ++i) {
                    fma2(acc[i][j], xa[i], wa);
                    fma2(acc[i][j], xb[i], wb);
                }
            }
        }
    }

    #pragma unroll
    for (int i = 0; i < 8; ++i)
        #pragma unroll
        for (int j = 0; j < 8; ++j) {
            unsigned long long v = acc[i][j];
            float s = __uint_as_float((unsigned)v) + __uint_as_float((unsigned)(v >> 32));
            g_part[((long)(ky * 32 + b0 + i)) * N + ntile + ng + 64 * j] = s;
        }
}

// ---------------- split-K reduce + bias + relu ----------------
__global__ void reduce_kernel(const float* __restrict__ bias, int osel, int N, int ks) {
    int idx = blockIdx.x * 256 + threadIdx.x;
    if (idx >= 32 * N) return;
    float s = bias[idx % N];
    for (int si = 0; si < ks; ++si) s += g_part[(long)si * 32 * N + idx];
    float* out = (osel == 1) ? g_act1 : (osel == 2) ? g_act2 : g_act3;
    out[idx] = fmaxf(s, 0.f);
}

// ---------------- dense4 (4096 -> 64) ----------------
__global__ void dense4_kernel(const float* __restrict__ w4, const float* __restrict__ b4) {
    int n = blockIdx.x, tid = threadIdx.x;
    float acc[32];
    #pragma unroll
    for (int b = 0; b < 32; ++b) acc[b] = 0.f;
    const float* wr = w4 + n * 4096;
    for (int k = tid; k < 4096; k += 128) {
        float w = wr[k];
        #pragma unroll
        for (int b = 0; b < 32; ++b) acc[b] += g_act3[b * 4096 + k] * w;
    }
    __shared__ float red[4][32];
    int lane = tid & 31, wrp = tid >> 5;
    #pragma unroll
    for (int b = 0; b < 32; ++b) {
        float v = acc[b];
        v += __shfl_down_sync(0xffffffffu, v, 16);
        v += __shfl_down_sync(0xffffffffu, v, 8);
        v += __shfl_down_sync(0xffffffffu, v, 4);
        v += __shfl_down_sync(0xffffffffu, v, 2);
        v += __shfl_down_sync(0xffffffffu, v, 1);
        if (lane == 0) red[wrp][b] = v;
    }
    __syncthreads();
    if (tid < 32) {
        float s = red[0][tid] + red[1][tid] + red[2][tid] + red[3][tid] + b4[n];
        g_act4[tid * 64 + n] = fmaxf(s, 0.f);
    }
}

// ---------------- fused output (64 -> 16 -> 1) ----------------
__global__ void final_kernel(const float* __restrict__ wo, const float* __restrict__ bo,
                             const float* __restrict__ wf, const float* __restrict__ bf,
                             float* __restrict__ out) {
    int b = threadIdx.x;   // 32 threads
    float res = bf[0];
    for (int j = 0; j < 16; ++j) {
        float o = bo[j];
        #pragma unroll
        for (int n = 0; n < 64; ++n) o += g_act4[b * 64 + n] * wo[j * 64 + n];
        res += o * wf[j];
    }
    out[b] = res;
}

extern "C" void kernel_launch(void* const* d_in, const int* in_sizes, int n_in,
                              void* d_out, int out_size) {
    const float* in  = (const float*)d_in[0];
    const float* cw  = (const float*)d_in[4];
    const float* cb  = (const float*)d_in[5];
    const float* w1  = (const float*)d_in[6];
    const float* b1  = (const float*)d_in[7];
    const float* w2  = (const float*)d_in[8];
    const float* b2  = (const float*)d_in[9];
    const float* w3  = (const float*)d_in[10];
    const float* b3  = (const float*)d_in[11];
    const float* w4  = (const float*)d_in[12];
    const float* b4  = (const float*)d_in[13];
    const float* wo  = (const float*)d_in[14];
    const float* bo  = (const float*)d_in[15];
    const float* wf  = (const float*)d_in[16];
    const float* bf  = (const float*)d_in[17];
    float* out = (float*)d_out;

    int smem = STAGES * (BN + 32) * SW * 4;   // 174,080 B
    cudaFuncSetAttribute(gemm_kernel, cudaFuncAttributeMaxDynamicSharedMemorySize, smem);

    conv_kernel<<<128, 128>>>(in, cw, cb);

    gemm_kernel<<<dim3(32, 4), 256, smem>>>(0, w1, 16384, 21504, 336);
    reduce_kernel<<<2048, 256>>>(b1, 1, 16384, 4);

    gemm_kernel<<<dim3(8, 16), 256, smem>>>(1, w2, 4096, 16384, 64);
    reduce_kernel<<<512, 256>>>(b2, 2, 4096, 16);

    gemm_kernel<<<dim3(8, 16), 256, smem>>>(2, w3, 4096, 4096, 16);
    reduce_kernel<<<512, 256>>>(b3, 3, 4096, 16);

    dense4_kernel<<<64, 128>>>(w4, b4);
    final_kernel<<<1, 32>>>(wo, bo, wf, bf, out);
}